// round 1
// baseline (speedup 1.0000x reference)
#include <cuda_runtime.h>
#include <math.h>

#define BGRAPH 64
#define NPG 512
#define NTOT (BGRAPH*NPG)      // 32768
#define NEDGE 524288
#define HDIM 128
#define KTOP 30
#define NCONV 32
#define TCONV 26               // K-4
#define FEAT (NCONV*TCONV)     // 832
#define FEAT2 (2*FEAT)         // 1664
#define NLAYER 4
#define TEMP_INV 2.0f
#define NEG_W 0.8f

// ---------------- scratch (device globals; no allocation allowed) ----------
__device__ float g_xcur[NTOT*HDIM];
__device__ float g_xw[NTOT*HDIM];
__device__ float g_agg[NTOT*HDIM];
__device__ float g_deg[NTOT];
__device__ float g_dis[NTOT];
__device__ float g_invdeg[NTOT];
__device__ float g_pool[BGRAPH*KTOP*HDIM];
__device__ float g_feat[2*BGRAPH*FEAT];
__device__ float g_scn[BGRAPH*FEAT];
__device__ float g_fcn[BGRAPH*FEAT];
__device__ float g_loss[1];
__device__ float g_logits[BGRAPH*2];

// ---------------- degree ---------------------------------------------------
__global__ void deg_count_kernel(const int* __restrict__ dst, float* __restrict__ deg) {
    int e = blockIdx.x * blockDim.x + threadIdx.x;
    if (e < NEDGE) atomicAdd(&deg[dst[e]], 1.0f);
}

__global__ void deg_finalize_kernel(const float* __restrict__ deg,
                                    float* __restrict__ dis, float* __restrict__ invdeg) {
    int i = blockIdx.x * blockDim.x + threadIdx.x;
    if (i < NTOT) {
        float d = deg[i] + 1.0f;
        dis[i] = rsqrtf(d);
        invdeg[i] = 1.0f / d;
    }
}

// ---------------- GEMM: Y[NTOT,128] = X[NTOT,128] @ W[128,128] -------------
// 256 threads, tile 64 rows x 128 cols, k-chunks of 32.
__global__ void gemm128_kernel(const float* __restrict__ X,
                               const float* __restrict__ W,
                               float* __restrict__ Y) {
    __shared__ float Xs[64][32];
    __shared__ float Ws[32][128];
    const int tid = threadIdx.x;
    const int tx = tid & 15;          // col group 0..15  (8 cols each)
    const int ty = tid >> 4;          // row group 0..15  (4 rows each)
    const int row0 = blockIdx.x * 64;

    float acc[4][8];
#pragma unroll
    for (int r = 0; r < 4; r++)
#pragma unroll
        for (int c = 0; c < 8; c++) acc[r][c] = 0.0f;

    for (int kc = 0; kc < HDIM; kc += 32) {
        // load W chunk: 32x128 = 1024 float4
#pragma unroll
        for (int q = 0; q < 4; q++) {
            int idx = q * 256 + tid;          // 0..1023
            int wr = idx >> 5;                // row 0..31
            int wc4 = idx & 31;               // col4 0..31
            float4 v = *(const float4*)&W[(kc + wr) * HDIM + wc4 * 4];
            *(float4*)&Ws[wr][wc4 * 4] = v;
        }
        // load X chunk: 64x32 = 512 float4
#pragma unroll
        for (int q = 0; q < 2; q++) {
            int idx = q * 256 + tid;          // 0..511
            int xr = idx >> 3;                // row 0..63
            int xc4 = idx & 7;                // col4 0..7
            float4 v = *(const float4*)&X[(row0 + xr) * HDIM + kc + xc4 * 4];
            *(float4*)&Xs[xr][xc4 * 4] = v;
        }
        __syncthreads();

#pragma unroll
        for (int k = 0; k < 32; k++) {
            float xv[4];
#pragma unroll
            for (int r = 0; r < 4; r++) xv[r] = Xs[ty * 4 + r][k];
            float4 w0 = *(const float4*)&Ws[k][tx * 8];
            float4 w1 = *(const float4*)&Ws[k][tx * 8 + 4];
            float wv[8] = {w0.x, w0.y, w0.z, w0.w, w1.x, w1.y, w1.z, w1.w};
#pragma unroll
            for (int r = 0; r < 4; r++)
#pragma unroll
                for (int c = 0; c < 8; c++)
                    acc[r][c] = fmaf(xv[r], wv[c], acc[r][c]);
        }
        __syncthreads();
    }

#pragma unroll
    for (int r = 0; r < 4; r++) {
        int row = row0 + ty * 4 + r;
        float4 o0 = make_float4(acc[r][0], acc[r][1], acc[r][2], acc[r][3]);
        float4 o1 = make_float4(acc[r][4], acc[r][5], acc[r][6], acc[r][7]);
        *(float4*)&Y[row * HDIM + tx * 8] = o0;
        *(float4*)&Y[row * HDIM + tx * 8 + 4] = o1;
    }
}

// ---------------- edge scatter: agg[dst] += dis[src]*dis[dst]*xw[src] ------
// one warp per edge; lane handles 4 consecutive channels.
__global__ void scatter_kernel(const int* __restrict__ src, const int* __restrict__ dst,
                               const float* __restrict__ dis,
                               const float* __restrict__ xw, float* __restrict__ agg) {
    int e = blockIdx.x * 8 + (threadIdx.x >> 5);
    int lane = threadIdx.x & 31;
    if (e >= NEDGE) return;
    int s = src[e], d = dst[e];
    float nrm = dis[s] * dis[d];
    float4 v = ((const float4*)(xw + (size_t)s * HDIM))[lane];
    float* ar = agg + (size_t)d * HDIM + lane * 4;
    atomicAdd(ar + 0, nrm * v.x);
    atomicAdd(ar + 1, nrm * v.y);
    atomicAdd(ar + 2, nrm * v.z);
    atomicAdd(ar + 3, nrm * v.w);
}

// ---------------- layer finalize: x = relu(agg + xw/deg + b) ---------------
__global__ void finalize_kernel(const float* __restrict__ agg, const float* __restrict__ xw,
                                const float* __restrict__ invdeg, const float* __restrict__ bias,
                                float* __restrict__ xout) {
    int i4 = blockIdx.x * blockDim.x + threadIdx.x;   // over NTOT*32 float4s
    if (i4 >= NTOT * (HDIM / 4)) return;
    int r = i4 >> 5;
    int c4 = i4 & 31;
    float id = invdeg[r];
    float4 a = ((const float4*)agg)[i4];
    float4 x = ((const float4*)xw)[i4];
    float4 b = ((const float4*)bias)[c4];
    float4 o;
    o.x = fmaxf(a.x + x.x * id + b.x, 0.0f);
    o.y = fmaxf(a.y + x.y * id + b.y, 0.0f);
    o.z = fmaxf(a.z + x.z * id + b.z, 0.0f);
    o.w = fmaxf(a.w + x.w * id + b.w, 0.0f);
    ((float4*)xout)[i4] = o;
}

// ---------------- sort pool: per-graph top-K by last channel (desc) --------
// bitonic sort of 512 (value desc, index asc on ties) matching jax.lax.top_k
__global__ void sortpool_kernel(const float* __restrict__ x, float* __restrict__ pool) {
    __shared__ float sv[NPG];
    __shared__ int si[NPG];
    int g = blockIdx.x;
    int tid = threadIdx.x;   // 512 threads
    sv[tid] = x[(g * NPG + tid) * HDIM + (HDIM - 1)];
    si[tid] = tid;
    __syncthreads();

    for (int k = 2; k <= NPG; k <<= 1) {
        for (int j = k >> 1; j > 0; j >>= 1) {
            int ixj = tid ^ j;
            if (ixj > tid) {
                float v1 = sv[tid], v2 = sv[ixj];
                int i1 = si[tid], i2 = si[ixj];
                // "before" in DESC order: bigger value first, tie -> lower index
                bool before12 = (v1 > v2) || (v1 == v2 && i1 < i2);
                bool descDir = ((tid & k) == 0);
                bool doswap = descDir ? (!before12) : before12;
                if (doswap) {
                    sv[tid] = v2; sv[ixj] = v1;
                    si[tid] = i2; si[ixj] = i1;
                }
            }
            __syncthreads();
        }
    }
    // gather top K rows
    for (int t = tid; t < KTOP * HDIM; t += NPG) {
        int kk = t / HDIM, c = t % HDIM;
        pool[(g * KTOP + kk) * HDIM + c] = x[(g * NPG + si[kk]) * HDIM + c];
    }
}

// ---------------- 1D conv head: [B,K,H] -> [B,32*26] -----------------------
__global__ void conv_kernel(const float* __restrict__ pool, const float* __restrict__ convW,
                            const float* __restrict__ convb, float* __restrict__ feat) {
    __shared__ float ps[KTOP * HDIM];   // 15 KB
    int g = blockIdx.x, tid = threadIdx.x;   // 256 threads
    for (int i = tid; i < KTOP * HDIM; i += 256) ps[i] = pool[g * KTOP * HDIM + i];
    __syncthreads();
    for (int u = tid; u < NCONV * TCONV; u += 256) {
        int o = u / TCONV, t = u % TCONV;
        const float* w = convW + o * HDIM * 5;
        float acc = convb[o];
        for (int h = 0; h < HDIM; h++) {
#pragma unroll
            for (int wd = 0; wd < 5; wd++)
                acc = fmaf(ps[(t + wd) * HDIM + h], w[h * 5 + wd], acc);
        }
        feat[g * FEAT + u] = fmaxf(acc, 0.0f);
    }
}

// ---------------- row L2-normalize -----------------------------------------
__global__ void normalize_kernel(const float* __restrict__ feat, float* __restrict__ out) {
    __shared__ float red[8];
    int b = blockIdx.x, tid = threadIdx.x;   // 256 threads
    float s = 0.0f;
    for (int i = tid; i < FEAT; i += 256) {
        float v = feat[b * FEAT + i];
        s += v * v;
    }
#pragma unroll
    for (int o = 16; o; o >>= 1) s += __shfl_xor_sync(0xFFFFFFFFu, s, o);
    if ((tid & 31) == 0) red[tid >> 5] = s;
    __syncthreads();
    if (tid == 0) {
        float t = 0.0f;
        for (int w = 0; w < 8; w++) t += red[w];
        red[0] = 1.0f / sqrtf(t);
    }
    __syncthreads();
    float inv = red[0];
    for (int i = tid; i < FEAT; i += 256) out[b * FEAT + i] = feat[b * FEAT + i] * inv;
}

// ---------------- CLIP loss -------------------------------------------------
__global__ void clip_kernel(const float* __restrict__ scn, const float* __restrict__ fcn,
                            float* __restrict__ loss) {
    __shared__ float sb[FEAT], fb[FEAT];
    __shared__ float dsf[BGRAPH], dss[BGRAPH], dfs[BGRAPH], dff[BGRAPH];
    int b = blockIdx.x, tid = threadIdx.x;   // 128 threads = 4 warps
    for (int i = tid; i < FEAT; i += 128) { sb[i] = scn[b * FEAT + i]; fb[i] = fcn[b * FEAT + i]; }
    __syncthreads();
    int warp = tid >> 5, lane = tid & 31;
    for (int j = warp; j < BGRAPH; j += 4) {
        float a_sf = 0, a_ss = 0, a_fs = 0, a_ff = 0;
        for (int i = lane; i < FEAT; i += 32) {
            float sj = scn[j * FEAT + i], fj = fcn[j * FEAT + i];
            a_sf = fmaf(sb[i], fj, a_sf);
            a_ss = fmaf(sb[i], sj, a_ss);
            a_fs = fmaf(fb[i], sj, a_fs);
            a_ff = fmaf(fb[i], fj, a_ff);
        }
#pragma unroll
        for (int o = 16; o; o >>= 1) {
            a_sf += __shfl_xor_sync(0xFFFFFFFFu, a_sf, o);
            a_ss += __shfl_xor_sync(0xFFFFFFFFu, a_ss, o);
            a_fs += __shfl_xor_sync(0xFFFFFFFFu, a_fs, o);
            a_ff += __shfl_xor_sync(0xFFFFFFFFu, a_ff, o);
        }
        if (lane == 0) { dsf[j] = a_sf; dss[j] = a_ss; dfs[j] = a_fs; dff[j] = a_ff; }
    }
    __syncthreads();
    if (tid == 0) {
        // sc row: [dsf/T , NEG_W * masked dss/T]
        float m1 = -1e30f, m2 = -1e30f;
        for (int j = 0; j < BGRAPH; j++) {
            float v = dsf[j] * TEMP_INV;
            float n = (j == b) ? 0.0f : NEG_W * dss[j] * TEMP_INV;
            m1 = fmaxf(m1, fmaxf(v, n));
            float v2 = dfs[j] * TEMP_INV;
            float n2 = (j == b) ? 0.0f : NEG_W * dff[j] * TEMP_INV;
            m2 = fmaxf(m2, fmaxf(v2, n2));
        }
        float s1 = 0.0f, s2 = 0.0f;
        for (int j = 0; j < BGRAPH; j++) {
            float v = dsf[j] * TEMP_INV;
            float n = (j == b) ? 0.0f : NEG_W * dss[j] * TEMP_INV;
            s1 += expf(v - m1) + expf(n - m1);
            float v2 = dfs[j] * TEMP_INV;
            float n2 = (j == b) ? 0.0f : NEG_W * dff[j] * TEMP_INV;
            s2 += expf(v2 - m2) + expf(n2 - m2);
        }
        float lse1 = m1 + logf(s1);
        float lse2 = m2 + logf(s2);
        float a = -(dsf[b] * TEMP_INV - lse1);
        float bb = -(dfs[b] * TEMP_INV - lse2);
        atomicAdd(loss, a + bb);
    }
}

// ---------------- MLP head --------------------------------------------------
__global__ void head_kernel(const float* __restrict__ featsc, const float* __restrict__ featfc,
                            const float* __restrict__ W1, const float* __restrict__ b1,
                            const float* __restrict__ W2, const float* __restrict__ b2,
                            const float* __restrict__ W3, const float* __restrict__ b3,
                            float* __restrict__ logits) {
    __shared__ float xr[FEAT2];
    __shared__ float h1[HDIM];
    __shared__ float h2[HDIM / 2];
    int b = blockIdx.x, tid = threadIdx.x;   // 128 threads
    for (int i = tid; i < FEAT; i += 128) {
        xr[i] = featsc[b * FEAT + i];
        xr[FEAT + i] = featfc[b * FEAT + i];
    }
    __syncthreads();
    {
        float acc = b1[tid];
        for (int i = 0; i < FEAT2; i++) acc = fmaf(xr[i], W1[i * HDIM + tid], acc);
        h1[tid] = fmaxf(acc, 0.0f);
    }
    __syncthreads();
    if (tid < 64) {
        float acc = b2[tid];
        for (int i = 0; i < HDIM; i++) acc = fmaf(h1[i], W2[i * 64 + tid], acc);
        h2[tid] = fmaxf(acc, 0.0f);
    }
    __syncthreads();
    if (tid < 2) {
        float acc = b3[tid];
        for (int i = 0; i < 64; i++) acc = fmaf(h2[i], W3[i * 2 + tid], acc);
        logits[b * 2 + tid] = acc;
    }
}

// ---------------- final output: log_softmax + loss -------------------------
__global__ void final_kernel(const float* __restrict__ logits, const float* __restrict__ loss,
                             float* __restrict__ out) {
    int b = threadIdx.x;
    if (b < BGRAPH) {
        float L = loss[0] * (1.0f / (2.0f * BGRAPH));
        float l0 = logits[b * 2], l1 = logits[b * 2 + 1];
        float m = fmaxf(l0, l1);
        float lse = m + logf(expf(l0 - m) + expf(l1 - m));
        out[b * 2] = l0 - lse + L;
        out[b * 2 + 1] = l1 - lse + L;
    }
}

// ---------------- host orchestration ---------------------------------------
extern "C" void kernel_launch(void* const* d_in, const int* in_sizes, int n_in,
                              void* d_out, int out_size) {
    (void)in_sizes; (void)n_in; (void)out_size;

    float *xcur, *xw, *agg, *deg, *dis, *invdeg, *pool, *feat, *scn, *fcn, *lossb, *logits;
    cudaGetSymbolAddress((void**)&xcur, g_xcur);
    cudaGetSymbolAddress((void**)&xw, g_xw);
    cudaGetSymbolAddress((void**)&agg, g_agg);
    cudaGetSymbolAddress((void**)&deg, g_deg);
    cudaGetSymbolAddress((void**)&dis, g_dis);
    cudaGetSymbolAddress((void**)&invdeg, g_invdeg);
    cudaGetSymbolAddress((void**)&pool, g_pool);
    cudaGetSymbolAddress((void**)&feat, g_feat);
    cudaGetSymbolAddress((void**)&scn, g_scn);
    cudaGetSymbolAddress((void**)&fcn, g_fcn);
    cudaGetSymbolAddress((void**)&lossb, g_loss);
    cudaGetSymbolAddress((void**)&logits, g_logits);

    for (int br = 0; br < 2; br++) {
        const float* x0 = (const float*)d_in[br];                 // sc_x / fc_x
        const int* src = (const int*)d_in[2 + br];                // edge_index row 0
        const int* dst = src + NEDGE;                             // row 1
        const float* Ws = (const float*)d_in[4 + 2 * br];
        const float* bs = (const float*)d_in[5 + 2 * br];
        const float* cW = (const float*)d_in[8 + 2 * br];
        const float* cb = (const float*)d_in[9 + 2 * br];

        cudaMemsetAsync(deg, 0, NTOT * sizeof(float), 0);
        deg_count_kernel<<<NEDGE / 256, 256>>>(dst, deg);
        deg_finalize_kernel<<<NTOT / 256, 256>>>(deg, dis, invdeg);

        const float* xin = x0;
        for (int l = 0; l < NLAYER; l++) {
            gemm128_kernel<<<NTOT / 64, 256>>>(xin, Ws + l * HDIM * HDIM, xw);
            cudaMemsetAsync(agg, 0, (size_t)NTOT * HDIM * sizeof(float), 0);
            scatter_kernel<<<NEDGE / 8, 256>>>(src, dst, dis, xw, agg);
            finalize_kernel<<<(NTOT * (HDIM / 4)) / 256, 256>>>(agg, xw, invdeg, bs + l * HDIM, xcur);
            xin = xcur;
        }
        sortpool_kernel<<<BGRAPH, NPG>>>(xcur, pool);
        conv_kernel<<<BGRAPH, 256>>>(pool, cW, cb, feat + br * BGRAPH * FEAT);
    }

    normalize_kernel<<<BGRAPH, 256>>>(feat, scn);
    normalize_kernel<<<BGRAPH, 256>>>(feat + BGRAPH * FEAT, fcn);
    cudaMemsetAsync(lossb, 0, sizeof(float), 0);
    clip_kernel<<<BGRAPH, 128>>>(scn, fcn, lossb);

    head_kernel<<<BGRAPH, 128>>>(feat, feat + BGRAPH * FEAT,
                                 (const float*)d_in[12], (const float*)d_in[13],
                                 (const float*)d_in[14], (const float*)d_in[15],
                                 (const float*)d_in[16], (const float*)d_in[17],
                                 logits);
    final_kernel<<<1, 64>>>(logits, lossb, (float*)d_out);
}

// round 2
// speedup vs baseline: 1.9830x; 1.9830x over previous
#include <cuda_runtime.h>
#include <math.h>

#define BGRAPH 64
#define NPG 512
#define NTOT (BGRAPH*NPG)      // 32768
#define NEDGE 524288
#define HDIM 128
#define KTOP 30
#define NCONV 32
#define TCONV 26               // K-4
#define FEAT (NCONV*TCONV)     // 832
#define FEAT2 (2*FEAT)         // 1664
#define NLAYER 4
#define TEMP_INV 2.0f
#define NEG_W 0.8f

// ---------------- scratch (device globals; no allocation allowed) ----------
__device__ float g_xcur[NTOT*HDIM];
__device__ float g_xw[NTOT*HDIM];
__device__ int   g_cnt[NTOT];
__device__ float g_dis[NTOT];
__device__ float g_invdeg[NTOT];
__device__ int   g_rowstart[NTOT+1];
__device__ int   g_cursor[NTOT];
__device__ int   g_csr_src[NEDGE];
__device__ float g_csr_nrm[NEDGE];
__device__ float g_pool[BGRAPH*KTOP*HDIM];
__device__ float g_feat[2*BGRAPH*FEAT];
__device__ float g_scn[BGRAPH*FEAT];
__device__ float g_fcn[BGRAPH*FEAT];
__device__ float g_loss[1];
__device__ float g_logits[BGRAPH*2];

// ---------------- degree count (int) ---------------------------------------
__global__ void deg_count_kernel(const int* __restrict__ dst, int* __restrict__ cnt) {
    int e = blockIdx.x * blockDim.x + threadIdx.x;
    if (e < NEDGE) atomicAdd(&cnt[dst[e]], 1);
}

__global__ void deg_finalize_kernel(const int* __restrict__ cnt,
                                    float* __restrict__ dis, float* __restrict__ invdeg) {
    int i = blockIdx.x * blockDim.x + threadIdx.x;
    if (i < NTOT) {
        float d = (float)cnt[i] + 1.0f;
        dis[i] = rsqrtf(d);
        invdeg[i] = 1.0f / d;
    }
}

// ---------------- exclusive prefix scan over NTOT counts (1 block) ---------
__global__ void scan_kernel(const int* __restrict__ cnt, int* __restrict__ rowstart) {
    __shared__ int warptot[32];
    const int tid = threadIdx.x;            // 1024 threads, 32 elems each
    const int base = tid * 32;
    int local[32];
    int s = 0;
#pragma unroll
    for (int i = 0; i < 32; i++) { local[i] = s; s += cnt[base + i]; }
    int lane = tid & 31, warp = tid >> 5;
    int v = s;
#pragma unroll
    for (int o = 1; o < 32; o <<= 1) {
        int t = __shfl_up_sync(0xFFFFFFFFu, v, o);
        if (lane >= o) v += t;
    }
    if (lane == 31) warptot[warp] = v;
    __syncthreads();
    if (warp == 0) {
        int w = warptot[lane];
#pragma unroll
        for (int o = 1; o < 32; o <<= 1) {
            int t = __shfl_up_sync(0xFFFFFFFFu, w, o);
            if (lane >= o) w += t;
        }
        warptot[lane] = w;
    }
    __syncthreads();
    int excl = (v - s) + (warp ? warptot[warp - 1] : 0);
#pragma unroll
    for (int i = 0; i < 32; i++) rowstart[base + i] = excl + local[i];
    if (tid == 1023) rowstart[NTOT] = excl + s;
}

// ---------------- CSR fill --------------------------------------------------
__global__ void csr_fill_kernel(const int* __restrict__ src, const int* __restrict__ dst,
                                const float* __restrict__ dis,
                                const int* __restrict__ rowstart, int* __restrict__ cursor,
                                int* __restrict__ csr_src, float* __restrict__ csr_nrm) {
    int e = blockIdx.x * blockDim.x + threadIdx.x;
    if (e >= NEDGE) return;
    int s = src[e], d = dst[e];
    int pos = atomicAdd(&cursor[d], 1);
    int idx = rowstart[d] + pos;
    csr_src[idx] = s;
    csr_nrm[idx] = dis[s] * dis[d];
}

// ---------------- GEMM: Y[NTOT,128] = X[NTOT,128] @ W[128,128] -------------
// 128x128 tile, 256 threads, 8x8 per thread, BK=16.
__global__ void gemm128_kernel(const float* __restrict__ X,
                               const float* __restrict__ W,
                               float* __restrict__ Y) {
    __shared__ float Xs[16][128];
    __shared__ float Ws[16][128];
    const int tid = threadIdx.x;
    const int tx = tid & 15;          // col group 0..15  (8 cols each)
    const int ty = tid >> 4;          // row group 0..15  (8 rows each)
    const int row0 = blockIdx.x * 128;

    float acc[8][8];
#pragma unroll
    for (int r = 0; r < 8; r++)
#pragma unroll
        for (int c = 0; c < 8; c++) acc[r][c] = 0.0f;

    for (int kc = 0; kc < HDIM; kc += 16) {
        // load X chunk: 128 rows x 16 k, transpose into Xs[k][row]
#pragma unroll
        for (int q = 0; q < 2; q++) {
            int idx = tid * 2 + q;            // 0..511
            int r = idx >> 2;                 // 0..127
            int k4 = (idx & 3) * 4;
            float4 v = *(const float4*)&X[(row0 + r) * HDIM + kc + k4];
            Xs[k4 + 0][r] = v.x;
            Xs[k4 + 1][r] = v.y;
            Xs[k4 + 2][r] = v.z;
            Xs[k4 + 3][r] = v.w;
        }
        // load W chunk: 16 k x 128 n (direct copy)
#pragma unroll
        for (int q = 0; q < 2; q++) {
            int idx = tid * 2 + q;            // 0..511
            int kr = idx >> 5;                // 0..15
            int c4 = (idx & 31) * 4;
            *(float4*)&Ws[kr][c4] = *(const float4*)&W[(kc + kr) * HDIM + c4];
        }
        __syncthreads();

#pragma unroll
        for (int k = 0; k < 16; k++) {
            float xv[8], wv[8];
            float4 x0 = *(const float4*)&Xs[k][ty * 8];
            float4 x1 = *(const float4*)&Xs[k][ty * 8 + 4];
            xv[0]=x0.x; xv[1]=x0.y; xv[2]=x0.z; xv[3]=x0.w;
            xv[4]=x1.x; xv[5]=x1.y; xv[6]=x1.z; xv[7]=x1.w;
            float4 w0 = *(const float4*)&Ws[k][tx * 8];
            float4 w1 = *(const float4*)&Ws[k][tx * 8 + 4];
            wv[0]=w0.x; wv[1]=w0.y; wv[2]=w0.z; wv[3]=w0.w;
            wv[4]=w1.x; wv[5]=w1.y; wv[6]=w1.z; wv[7]=w1.w;
#pragma unroll
            for (int r = 0; r < 8; r++)
#pragma unroll
                for (int c = 0; c < 8; c++)
                    acc[r][c] = fmaf(xv[r], wv[c], acc[r][c]);
        }
        __syncthreads();
    }

#pragma unroll
    for (int r = 0; r < 8; r++) {
        int row = row0 + ty * 8 + r;
        float4 o0 = make_float4(acc[r][0], acc[r][1], acc[r][2], acc[r][3]);
        float4 o1 = make_float4(acc[r][4], acc[r][5], acc[r][6], acc[r][7]);
        *(float4*)&Y[row * HDIM + tx * 8] = o0;
        *(float4*)&Y[row * HDIM + tx * 8 + 4] = o1;
    }
}

// ---------------- fused gather-aggregate + self-loop + bias + relu ---------
// one warp per dst node; lane handles 4 consecutive channels (float4).
__global__ void agg_kernel(const int* __restrict__ rowstart,
                           const int* __restrict__ csr_src, const float* __restrict__ csr_nrm,
                           const float* __restrict__ xw, const float* __restrict__ invdeg,
                           const float* __restrict__ bias, float* __restrict__ xout) {
    int node = blockIdx.x * 8 + (threadIdx.x >> 5);
    int lane = threadIdx.x & 31;
    int j = rowstart[node], jend = rowstart[node + 1];
    float4 acc = make_float4(0.f, 0.f, 0.f, 0.f);
    for (; j + 1 < jend; j += 2) {
        int sA = csr_src[j], sB = csr_src[j + 1];
        float nA = csr_nrm[j], nB = csr_nrm[j + 1];
        float4 vA = ((const float4*)(xw + (size_t)sA * HDIM))[lane];
        float4 vB = ((const float4*)(xw + (size_t)sB * HDIM))[lane];
        acc.x += nA * vA.x + nB * vB.x;
        acc.y += nA * vA.y + nB * vB.y;
        acc.z += nA * vA.z + nB * vB.z;
        acc.w += nA * vA.w + nB * vB.w;
    }
    if (j < jend) {
        int sA = csr_src[j];
        float nA = csr_nrm[j];
        float4 vA = ((const float4*)(xw + (size_t)sA * HDIM))[lane];
        acc.x += nA * vA.x; acc.y += nA * vA.y;
        acc.z += nA * vA.z; acc.w += nA * vA.w;
    }
    float id = invdeg[node];
    float4 xs = ((const float4*)(xw + (size_t)node * HDIM))[lane];
    float4 b = ((const float4*)bias)[lane];
    float4 o;
    o.x = fmaxf(acc.x + xs.x * id + b.x, 0.0f);
    o.y = fmaxf(acc.y + xs.y * id + b.y, 0.0f);
    o.z = fmaxf(acc.z + xs.z * id + b.z, 0.0f);
    o.w = fmaxf(acc.w + xs.w * id + b.w, 0.0f);
    ((float4*)(xout + (size_t)node * HDIM))[lane] = o;
}

// ---------------- sort pool: per-graph top-K by last channel (desc) --------
__global__ void sortpool_kernel(const float* __restrict__ x, float* __restrict__ pool) {
    __shared__ float sv[NPG];
    __shared__ int si[NPG];
    int g = blockIdx.x;
    int tid = threadIdx.x;   // 512 threads
    sv[tid] = x[(g * NPG + tid) * HDIM + (HDIM - 1)];
    si[tid] = tid;
    __syncthreads();

    for (int k = 2; k <= NPG; k <<= 1) {
        for (int j = k >> 1; j > 0; j >>= 1) {
            int ixj = tid ^ j;
            if (ixj > tid) {
                float v1 = sv[tid], v2 = sv[ixj];
                int i1 = si[tid], i2 = si[ixj];
                bool before12 = (v1 > v2) || (v1 == v2 && i1 < i2);
                bool descDir = ((tid & k) == 0);
                bool doswap = descDir ? (!before12) : before12;
                if (doswap) {
                    sv[tid] = v2; sv[ixj] = v1;
                    si[tid] = i2; si[ixj] = i1;
                }
            }
            __syncthreads();
        }
    }
    for (int t = tid; t < KTOP * HDIM; t += NPG) {
        int kk = t / HDIM, c = t % HDIM;
        pool[(g * KTOP + kk) * HDIM + c] = x[(g * NPG + si[kk]) * HDIM + c];
    }
}

// ---------------- 1D conv head: [B,K,H] -> [B,32*26] -----------------------
__global__ void conv_kernel(const float* __restrict__ pool, const float* __restrict__ convW,
                            const float* __restrict__ convb, float* __restrict__ feat) {
    __shared__ float ps[KTOP * HDIM];   // 15 KB
    int g = blockIdx.x, tid = threadIdx.x;   // 256 threads
    for (int i = tid; i < KTOP * HDIM; i += 256) ps[i] = pool[g * KTOP * HDIM + i];
    __syncthreads();
    for (int u = tid; u < NCONV * TCONV; u += 256) {
        int o = u / TCONV, t = u % TCONV;
        const float* w = convW + o * HDIM * 5;
        float acc = convb[o];
        for (int h = 0; h < HDIM; h++) {
#pragma unroll
            for (int wd = 0; wd < 5; wd++)
                acc = fmaf(ps[(t + wd) * HDIM + h], w[h * 5 + wd], acc);
        }
        feat[g * FEAT + u] = fmaxf(acc, 0.0f);
    }
}

// ---------------- row L2-normalize -----------------------------------------
__global__ void normalize_kernel(const float* __restrict__ feat, float* __restrict__ out) {
    __shared__ float red[8];
    int b = blockIdx.x, tid = threadIdx.x;   // 256 threads
    float s = 0.0f;
    for (int i = tid; i < FEAT; i += 256) {
        float v = feat[b * FEAT + i];
        s += v * v;
    }
#pragma unroll
    for (int o = 16; o; o >>= 1) s += __shfl_xor_sync(0xFFFFFFFFu, s, o);
    if ((tid & 31) == 0) red[tid >> 5] = s;
    __syncthreads();
    if (tid == 0) {
        float t = 0.0f;
        for (int w = 0; w < 8; w++) t += red[w];
        red[0] = 1.0f / sqrtf(t);
    }
    __syncthreads();
    float inv = red[0];
    for (int i = tid; i < FEAT; i += 256) out[b * FEAT + i] = feat[b * FEAT + i] * inv;
}

// ---------------- CLIP loss -------------------------------------------------
__global__ void clip_kernel(const float* __restrict__ scn, const float* __restrict__ fcn,
                            float* __restrict__ loss) {
    __shared__ float sb[FEAT], fb[FEAT];
    __shared__ float dsf[BGRAPH], dss[BGRAPH], dfs[BGRAPH], dff[BGRAPH];
    int b = blockIdx.x, tid = threadIdx.x;   // 128 threads = 4 warps
    for (int i = tid; i < FEAT; i += 128) { sb[i] = scn[b * FEAT + i]; fb[i] = fcn[b * FEAT + i]; }
    __syncthreads();
    int warp = tid >> 5, lane = tid & 31;
    for (int j = warp; j < BGRAPH; j += 4) {
        float a_sf = 0, a_ss = 0, a_fs = 0, a_ff = 0;
        for (int i = lane; i < FEAT; i += 32) {
            float sj = scn[j * FEAT + i], fj = fcn[j * FEAT + i];
            a_sf = fmaf(sb[i], fj, a_sf);
            a_ss = fmaf(sb[i], sj, a_ss);
            a_fs = fmaf(fb[i], sj, a_fs);
            a_ff = fmaf(fb[i], fj, a_ff);
        }
#pragma unroll
        for (int o = 16; o; o >>= 1) {
            a_sf += __shfl_xor_sync(0xFFFFFFFFu, a_sf, o);
            a_ss += __shfl_xor_sync(0xFFFFFFFFu, a_ss, o);
            a_fs += __shfl_xor_sync(0xFFFFFFFFu, a_fs, o);
            a_ff += __shfl_xor_sync(0xFFFFFFFFu, a_ff, o);
        }
        if (lane == 0) { dsf[j] = a_sf; dss[j] = a_ss; dfs[j] = a_fs; dff[j] = a_ff; }
    }
    __syncthreads();
    if (tid == 0) {
        float m1 = -1e30f, m2 = -1e30f;
        for (int j = 0; j < BGRAPH; j++) {
            float v = dsf[j] * TEMP_INV;
            float n = (j == b) ? 0.0f : NEG_W * dss[j] * TEMP_INV;
            m1 = fmaxf(m1, fmaxf(v, n));
            float v2 = dfs[j] * TEMP_INV;
            float n2 = (j == b) ? 0.0f : NEG_W * dff[j] * TEMP_INV;
            m2 = fmaxf(m2, fmaxf(v2, n2));
        }
        float s1 = 0.0f, s2 = 0.0f;
        for (int j = 0; j < BGRAPH; j++) {
            float v = dsf[j] * TEMP_INV;
            float n = (j == b) ? 0.0f : NEG_W * dss[j] * TEMP_INV;
            s1 += expf(v - m1) + expf(n - m1);
            float v2 = dfs[j] * TEMP_INV;
            float n2 = (j == b) ? 0.0f : NEG_W * dff[j] * TEMP_INV;
            s2 += expf(v2 - m2) + expf(n2 - m2);
        }
        float lse1 = m1 + logf(s1);
        float lse2 = m2 + logf(s2);
        float a = -(dsf[b] * TEMP_INV - lse1);
        float bb = -(dfs[b] * TEMP_INV - lse2);
        atomicAdd(loss, a + bb);
    }
}

// ---------------- MLP head --------------------------------------------------
__global__ void head_kernel(const float* __restrict__ featsc, const float* __restrict__ featfc,
                            const float* __restrict__ W1, const float* __restrict__ b1,
                            const float* __restrict__ W2, const float* __restrict__ b2,
                            const float* __restrict__ W3, const float* __restrict__ b3,
                            float* __restrict__ logits) {
    __shared__ float xr[FEAT2];
    __shared__ float h1[HDIM];
    __shared__ float h2[HDIM / 2];
    int b = blockIdx.x, tid = threadIdx.x;   // 128 threads
    for (int i = tid; i < FEAT; i += 128) {
        xr[i] = featsc[b * FEAT + i];
        xr[FEAT + i] = featfc[b * FEAT + i];
    }
    __syncthreads();
    {
        float acc = b1[tid];
        for (int i = 0; i < FEAT2; i++) acc = fmaf(xr[i], W1[i * HDIM + tid], acc);
        h1[tid] = fmaxf(acc, 0.0f);
    }
    __syncthreads();
    if (tid < 64) {
        float acc = b2[tid];
        for (int i = 0; i < HDIM; i++) acc = fmaf(h1[i], W2[i * 64 + tid], acc);
        h2[tid] = fmaxf(acc, 0.0f);
    }
    __syncthreads();
    if (tid < 2) {
        float acc = b3[tid];
        for (int i = 0; i < 64; i++) acc = fmaf(h2[i], W3[i * 2 + tid], acc);
        logits[b * 2 + tid] = acc;
    }
}

// ---------------- final output: log_softmax + loss -------------------------
__global__ void final_kernel(const float* __restrict__ logits, const float* __restrict__ loss,
                             float* __restrict__ out) {
    int b = threadIdx.x;
    if (b < BGRAPH) {
        float L = loss[0] * (1.0f / (2.0f * BGRAPH));
        float l0 = logits[b * 2], l1 = logits[b * 2 + 1];
        float m = fmaxf(l0, l1);
        float lse = m + logf(expf(l0 - m) + expf(l1 - m));
        out[b * 2] = l0 - lse + L;
        out[b * 2 + 1] = l1 - lse + L;
    }
}

// ---------------- host orchestration ---------------------------------------
extern "C" void kernel_launch(void* const* d_in, const int* in_sizes, int n_in,
                              void* d_out, int out_size) {
    (void)in_sizes; (void)n_in; (void)out_size;

    float *xcur, *xw, *dis, *invdeg, *pool, *feat, *scn, *fcn, *lossb, *logits, *csr_nrm;
    int *cnt, *rowstart, *cursor, *csr_src;
    cudaGetSymbolAddress((void**)&xcur, g_xcur);
    cudaGetSymbolAddress((void**)&xw, g_xw);
    cudaGetSymbolAddress((void**)&cnt, g_cnt);
    cudaGetSymbolAddress((void**)&dis, g_dis);
    cudaGetSymbolAddress((void**)&invdeg, g_invdeg);
    cudaGetSymbolAddress((void**)&rowstart, g_rowstart);
    cudaGetSymbolAddress((void**)&cursor, g_cursor);
    cudaGetSymbolAddress((void**)&csr_src, g_csr_src);
    cudaGetSymbolAddress((void**)&csr_nrm, g_csr_nrm);
    cudaGetSymbolAddress((void**)&pool, g_pool);
    cudaGetSymbolAddress((void**)&feat, g_feat);
    cudaGetSymbolAddress((void**)&scn, g_scn);
    cudaGetSymbolAddress((void**)&fcn, g_fcn);
    cudaGetSymbolAddress((void**)&lossb, g_loss);
    cudaGetSymbolAddress((void**)&logits, g_logits);

    for (int br = 0; br < 2; br++) {
        const float* x0 = (const float*)d_in[br];                 // sc_x / fc_x
        const int* src = (const int*)d_in[2 + br];                // edge_index row 0
        const int* dst = src + NEDGE;                             // row 1
        const float* Ws = (const float*)d_in[4 + 2 * br];
        const float* bs = (const float*)d_in[5 + 2 * br];
        const float* cW = (const float*)d_in[8 + 2 * br];
        const float* cb = (const float*)d_in[9 + 2 * br];

        // --- CSR build (once per branch, reused across 4 layers) ---
        cudaMemsetAsync(cnt, 0, NTOT * sizeof(int), 0);
        deg_count_kernel<<<NEDGE / 256, 256>>>(dst, cnt);
        deg_finalize_kernel<<<NTOT / 256, 256>>>(cnt, dis, invdeg);
        scan_kernel<<<1, 1024>>>(cnt, rowstart);
        cudaMemsetAsync(cursor, 0, NTOT * sizeof(int), 0);
        csr_fill_kernel<<<NEDGE / 256, 256>>>(src, dst, dis, rowstart, cursor, csr_src, csr_nrm);

        const float* xin = x0;
        for (int l = 0; l < NLAYER; l++) {
            gemm128_kernel<<<NTOT / 128, 256>>>(xin, Ws + l * HDIM * HDIM, xw);
            agg_kernel<<<NTOT / 8, 256>>>(rowstart, csr_src, csr_nrm, xw, invdeg,
                                          bs + l * HDIM, xcur);
            xin = xcur;
        }
        sortpool_kernel<<<BGRAPH, NPG>>>(xcur, pool);
        conv_kernel<<<BGRAPH, 256>>>(pool, cW, cb, feat + br * BGRAPH * FEAT);
    }

    normalize_kernel<<<BGRAPH, 256>>>(feat, scn);
    normalize_kernel<<<BGRAPH, 256>>>(feat + BGRAPH * FEAT, fcn);
    cudaMemsetAsync(lossb, 0, sizeof(float), 0);
    clip_kernel<<<BGRAPH, 128>>>(scn, fcn, lossb);

    head_kernel<<<BGRAPH, 128>>>(feat, feat + BGRAPH * FEAT,
                                 (const float*)d_in[12], (const float*)d_in[13],
                                 (const float*)d_in[14], (const float*)d_in[15],
                                 (const float*)d_in[16], (const float*)d_in[17],
                                 logits);
    final_kernel<<<1, 64>>>(logits, lossb, (float*)d_out);
}